// round 1
// baseline (speedup 1.0000x reference)
#include <cuda_runtime.h>
#include <stdint.h>

#define DIMO 7
#define KOUT 49
#define MAXT 32
#define SAMPLES_PER_BLK 32
#define THREADS_PER_BLK 64
#define XSTR 99                    // words per lane X-blob: X1[0..48] X2[49..97] pad  (99 mod 32 = 3, odd -> conflict-free)
#define WBASE (SAMPLES_PER_BLK * XSTR)          // 3168 words
#define WSTR 49                                  // per-thread W stride (49 mod 32 = 17, odd)
#define OBASE (WBASE + THREADS_PER_BLK * WSTR)   // 6304 words
#define OUTSTR 33                                // out_s[k*33 + s]
#define SMEM_WORDS (OBASE + KOUT * OUTSTR)       // 7921 words = 31684 B (fits static smem)

// ---- device tables built by setup kernel each launch ----
__device__ int   g_T[8];            // T[0..6] term counts per row, g_T[7] = Ttot (unused by main)
__device__ uint4 g_s1[7 * MAXT];    // stage1: {x1_row_byteoff, x2_row_byteoff, c (f32 bits), pad}
__device__ uint2 g_s2[7 * MAXT];    // stage2: {W_byteoff, d (f32 bits)}

// ---------------------------------------------------------------------------
// Setup kernel: recover the factorized term lists from the aligned product
// arrays. Generation order is (mu outer, t, mup, t'), so:
//   - first occurrence of mu_both value v (v<7)   -> start of (mu=0,t=0,mup=v) run
//   - first occurrence of value mu*7              -> start of mu segment
//   - T[v] = focc[v+1]-focc[v] for v<6 ; T[6] = focc[7]/T[0] - focc[6]
//   - Ttot = focc[6] + T[6]
// Coefficient recovery from products only (A = mult[0] = c0^2):
//   stage1 c_hat(mu,t)  = mult[ seg(mu) + t*Ttot ]          (= c_t * c0)
//   stage2 d_hat(mup,t')= mult[ focc[mup] + t' ] / A         (= c_t' / c0)
//   => c_hat * d_hat = c_t * c_t'   (exact, no sign/sqrt issues)
// ---------------------------------------------------------------------------
__global__ void wigner_setup(const float* __restrict__ mult,
                             const int* __restrict__ m1,  const int* __restrict__ m1p,
                             const int* __restrict__ m2,  const int* __restrict__ m2p,
                             const int* __restrict__ mub, int n)
{
    __shared__ int focc[KOUT];
    __shared__ int sT[8];
    int tid = threadIdx.x;
    if (tid < KOUT) focc[tid] = 0x7fffffff;
    __syncthreads();
    for (int j = tid; j < n; j += blockDim.x)
        atomicMin(&focc[mub[j]], j);
    __syncthreads();
    if (tid == 0) {
        int T0 = focc[1] - focc[0];                 // focc[0] == 0
        sT[0] = T0;
        for (int v = 1; v < 6; v++) sT[v] = focc[v + 1] - focc[v];
        int t6 = focc[7] / T0 - focc[6];
        sT[6] = t6;
        sT[7] = focc[6] + t6;                       // Ttot
        for (int v = 0; v < 7; v++) if (sT[v] > MAXT) sT[v] = MAXT;  // safety clamp
    }
    __syncthreads();
    if (tid < 8) g_T[tid] = sT[tid];
    float A = mult[0];
    int Ttot = sT[7];
    if (tid < 7 * MAXT) {
        int mu = tid >> 5;
        int t  = tid & 31;
        if (t < sT[mu]) {
            // stage1 entry: aligned index of (mu, t, mup=0, t'=0)
            int j = focc[mu * 7] + t * Ttot;
            g_s1[tid] = make_uint4((unsigned)(m1[j] * 28),            // X1 row byte offset (row*7 floats)
                                   (unsigned)(196 + m2[j] * 28),      // X2 region at word 49 -> byte 196
                                   __float_as_uint(mult[j]), 0u);
            // stage2 entry: aligned index of (mu=0, t=0, mup=mu, t'=t)
            int j2 = focc[mu] + t;
            g_s2[tid] = make_uint2((unsigned)((m1p[j2] * 7 + m2p[j2]) * 4),  // offset within per-thread W
                                   __float_as_uint(mult[j2] / A));
        }
    }
}

// ---------------------------------------------------------------------------
// Main kernel: 32 samples per block (thread-per-sample), 2 warps split the
// mu loop by parity. X1/X2 staged per-lane in shared (odd stride -> all 32
// lanes hit distinct banks on every broadcast-index gather). W per thread in
// shared for the stage-2 gather. Output staged transposed for coalesced flush.
// ---------------------------------------------------------------------------
__global__ void __launch_bounds__(THREADS_PER_BLK)
wigner_main(const float* __restrict__ X1, const float* __restrict__ X2,
            float* __restrict__ out, int N)
{
    __shared__ float sm[SMEM_WORDS];
    int tid  = threadIdx.x;
    int lane = tid & 31;
    int w    = tid >> 5;
    int base = blockIdx.x * SAMPLES_PER_BLK;
    int nvalid = N - base; if (nvalid > SAMPLES_PER_BLK) nvalid = SAMPLES_PER_BLK;
    int total = nvalid * KOUT;

    const float* g1 = X1 + (size_t)base * KOUT;
    const float* g2 = X2 + (size_t)base * KOUT;

    // stage in: coalesced global -> per-lane blobs
    for (int i = tid; i < total; i += THREADS_PER_BLK) {
        int s = i / KOUT;
        int c = i - s * KOUT;
        sm[s * XSTR + c]      = g1[i];
        sm[s * XSTR + 49 + c] = g2[i];
    }
    __syncthreads();

    if (lane < nvalid) {
        const char* xc = (const char*)(sm + lane * XSTR);
        float*      wp = sm + WBASE + tid * WSTR;
        const char* wc = (const char*)wp;

        int Ts[7];
        #pragma unroll
        for (int v = 0; v < 7; v++) Ts[v] = __ldg(&g_T[v]);

        // warp 0: mu = 0,2,4,6 ; warp 1: mu = 1,3,5  (parity split for balance)
        #pragma unroll 1
        for (int mu = w; mu < 7; mu += 2) {
            float W[49];
            #pragma unroll
            for (int i = 0; i < 49; i++) W[i] = 0.0f;

            const uint4* s1 = g_s1 + mu * MAXT;
            int Tmu = Ts[mu];
            for (int t = 0; t < Tmu; t++) {
                uint4 e = __ldg(&s1[t]);                 // broadcast across warp
                float c = __uint_as_float(e.z);
                const float* r1 = (const float*)(xc + e.x);
                const float* r2 = (const float*)(xc + e.y);
                float x2v[7];
                #pragma unroll
                for (int b = 0; b < 7; b++) x2v[b] = r2[b];
                #pragma unroll
                for (int a = 0; a < 7; a++) {
                    float t1 = c * r1[a];
                    #pragma unroll
                    for (int b = 0; b < 7; b++)
                        W[a * 7 + b] = fmaf(t1, x2v[b], W[a * 7 + b]);
                }
            }
            // spill W to shared for the dynamic stage-2 gather
            #pragma unroll
            for (int i = 0; i < 49; i++) wp[i] = W[i];

            #pragma unroll 1
            for (int mup = 0; mup < 7; mup++) {
                const uint2* s2 = g_s2 + mup * MAXT;
                int Tp = Ts[mup];
                float a0 = 0.0f, a1 = 0.0f;
                int tp = 0;
                for (; tp + 2 <= Tp; tp += 2) {
                    uint2 e0 = __ldg(&s2[tp]);
                    uint2 e1 = __ldg(&s2[tp + 1]);
                    a0 = fmaf(__uint_as_float(e0.y), *(const float*)(wc + e0.x), a0);
                    a1 = fmaf(__uint_as_float(e1.y), *(const float*)(wc + e1.x), a1);
                }
                if (tp < Tp) {
                    uint2 e0 = __ldg(&s2[tp]);
                    a0 = fmaf(__uint_as_float(e0.y), *(const float*)(wc + e0.x), a0);
                }
                sm[OBASE + (mu * 7 + mup) * OUTSTR + lane] = a0 + a1;
            }
        }
    }
    __syncthreads();

    // flush: transposed shared -> coalesced global
    float* go = out + (size_t)base * KOUT;
    for (int i = tid; i < total; i += THREADS_PER_BLK) {
        int s = i / KOUT;
        int c = i - s * KOUT;
        go[i] = sm[OBASE + c * OUTSTR + s];
    }
}

// ---------------------------------------------------------------------------
extern "C" void kernel_launch(void* const* d_in, const int* in_sizes, int n_in,
                              void* d_out, int out_size)
{
    const float* X1   = (const float*)d_in[0];
    const float* X2   = (const float*)d_in[1];
    const float* mult = (const float*)d_in[2];
    const int*   m1   = (const int*)d_in[3];
    const int*   m1p  = (const int*)d_in[4];
    const int*   m2   = (const int*)d_in[5];
    const int*   m2p  = (const int*)d_in[6];
    const int*   mub  = (const int*)d_in[7];

    int n_aligned = in_sizes[2];
    int N = in_sizes[0] / KOUT;

    wigner_setup<<<1, 256>>>(mult, m1, m1p, m2, m2p, mub, n_aligned);

    int grid = (N + SAMPLES_PER_BLK - 1) / SAMPLES_PER_BLK;
    wigner_main<<<grid, THREADS_PER_BLK>>>(X1, X2, (float*)d_out, N);
}